// round 1
// baseline (speedup 1.0000x reference)
#include <cuda_runtime.h>

#define NNODES 200000
#define NEDGES 6400000
#define AF 82
#define H 10
#define ED 6
#define AGG_STRIDE 12   // pad 10 -> 12 floats so rows are 48B (16B-aligned) for red.v4

__device__ float g_h[(size_t)NNODES * H];
__device__ float g_agg[(size_t)NNODES * AGG_STRIDE];

__device__ __forceinline__ float lrelu(float x) { return fmaxf(x, 0.1f * x); }

// h = lrelu(vertex @ Wi)   [N,82] @ [82,10]
__global__ void init_kernel(const float* __restrict__ vertex,
                            const float* __restrict__ Wi, int n) {
    __shared__ float w[AF * H];
    for (int i = threadIdx.x; i < AF * H; i += blockDim.x) w[i] = Wi[i];
    __syncthreads();
    int node = blockIdx.x * blockDim.x + threadIdx.x;
    if (node >= n) return;
    const float2* vr = (const float2*)(vertex + (size_t)node * AF);
    float acc[H];
#pragma unroll
    for (int j = 0; j < H; j++) acc[j] = 0.f;
#pragma unroll
    for (int i = 0; i < AF / 2; i++) {
        float2 v = vr[i];
#pragma unroll
        for (int j = 0; j < H; j++)
            acc[j] += v.x * w[(2 * i) * H + j] + v.y * w[(2 * i + 1) * H + j];
    }
    float2* hr = (float2*)(g_h + (size_t)node * H);
#pragma unroll
    for (int j = 0; j < H / 2; j++) {
        float2 o;
        o.x = lrelu(acc[2 * j]);
        o.y = lrelu(acc[2 * j + 1]);
        hr[j] = o;
    }
}

// per-edge: msg = lrelu([h[src], ef] @ Wg); agg[dst] += msg  (vector red.global)
__global__ void edge_kernel(const float* __restrict__ ef,
                            const int* __restrict__ src,
                            const int* __restrict__ dst,
                            const float* __restrict__ Wg, int ecnt) {
    __shared__ float w[(H + ED) * H];
    for (int i = threadIdx.x; i < (H + ED) * H; i += blockDim.x) w[i] = Wg[i];
    __syncthreads();
    int e = blockIdx.x * blockDim.x + threadIdx.x;
    if (e >= ecnt) return;
    int s = src[e];
    int d = dst[e];

    float hs[H];
    const float2* hr = (const float2*)(g_h + (size_t)s * H);
#pragma unroll
    for (int i = 0; i < H / 2; i++) {
        float2 v = hr[i];
        hs[2 * i] = v.x;
        hs[2 * i + 1] = v.y;
    }
    float ev[ED];
    const float2* er = (const float2*)(ef + (size_t)e * ED);
#pragma unroll
    for (int i = 0; i < ED / 2; i++) {
        float2 v = er[i];
        ev[2 * i] = v.x;
        ev[2 * i + 1] = v.y;
    }

    float m[H];
#pragma unroll
    for (int j = 0; j < H; j++) {
        float a = 0.f;
#pragma unroll
        for (int i = 0; i < H; i++) a += hs[i] * w[i * H + j];
#pragma unroll
        for (int k = 0; k < ED; k++) a += ev[k] * w[(H + k) * H + j];
        m[j] = lrelu(a);
    }

    float* ap = g_agg + (size_t)d * AGG_STRIDE;
    asm volatile("red.global.add.v4.f32 [%0], {%1,%2,%3,%4};" ::"l"(ap),
                 "f"(m[0]), "f"(m[1]), "f"(m[2]), "f"(m[3])
                 : "memory");
    asm volatile("red.global.add.v4.f32 [%0], {%1,%2,%3,%4};" ::"l"(ap + 4),
                 "f"(m[4]), "f"(m[5]), "f"(m[6]), "f"(m[7])
                 : "memory");
    asm volatile("red.global.add.v2.f32 [%0], {%1,%2};" ::"l"(ap + 8),
                 "f"(m[8]), "f"(m[9])
                 : "memory");
}

// h_out = lrelu([h, agg] @ Wu)
__global__ void update_kernel(const float* __restrict__ Wu, float* out, int n) {
    __shared__ float w[2 * H * H];
    for (int i = threadIdx.x; i < 2 * H * H; i += blockDim.x) w[i] = Wu[i];
    __syncthreads();
    int node = blockIdx.x * blockDim.x + threadIdx.x;
    if (node >= n) return;

    float hv[2 * H];
    const float2* hr = (const float2*)(g_h + (size_t)node * H);
#pragma unroll
    for (int i = 0; i < H / 2; i++) {
        float2 v = hr[i];
        hv[2 * i] = v.x;
        hv[2 * i + 1] = v.y;
    }
    const float4* ar = (const float4*)(g_agg + (size_t)node * AGG_STRIDE);
    float av[12];
#pragma unroll
    for (int i = 0; i < 3; i++) {
        float4 v = ar[i];
        av[4 * i] = v.x;
        av[4 * i + 1] = v.y;
        av[4 * i + 2] = v.z;
        av[4 * i + 3] = v.w;
    }
#pragma unroll
    for (int i = 0; i < H; i++) hv[H + i] = av[i];

    float o[H];
#pragma unroll
    for (int j = 0; j < H; j++) {
        float a = 0.f;
#pragma unroll
        for (int i = 0; i < 2 * H; i++) a += hv[i] * w[i * H + j];
        o[j] = lrelu(a);
    }
    float2* orow = (float2*)(out + (size_t)node * H);
#pragma unroll
    for (int j = 0; j < H / 2; j++) {
        float2 t;
        t.x = o[2 * j];
        t.y = o[2 * j + 1];
        orow[j] = t;
    }
}

extern "C" void kernel_launch(void* const* d_in, const int* in_sizes, int n_in,
                              void* d_out, int out_size) {
    const float* vertex = (const float*)d_in[0];
    const float* ef = (const float*)d_in[1];
    const int* src = (const int*)d_in[2];
    const int* dst = (const int*)d_in[3];
    const float* Wi = (const float*)d_in[4];
    const float* Wg = (const float*)d_in[5];
    const float* Wu = (const float*)d_in[6];
    float* out = (float*)d_out;

    int n = in_sizes[0] / AF;
    int e = in_sizes[2];

    void* aggp = nullptr;
    void* hp = nullptr;
    cudaGetSymbolAddress(&aggp, g_agg);
    cudaGetSymbolAddress(&hp, g_h);

    int nb = (n + 255) / 256;
    int eb = (e + 255) / 256;

    init_kernel<<<nb, 256>>>(vertex, Wi, n);
    for (int l = 0; l < 2; l++) {
        cudaMemsetAsync(aggp, 0, (size_t)n * AGG_STRIDE * sizeof(float));
        edge_kernel<<<eb, 256>>>(ef, src, dst, Wg, e);
        update_kernel<<<nb, 256>>>(Wu, (l == 1) ? out : (float*)hp, n);
    }
}